// round 2
// baseline (speedup 1.0000x reference)
#include <cuda_runtime.h>
#include <cuda_bf16.h>
#include <cstdint>

// Problem constants (fixed by setup_inputs)
#define BB 8
#define TT 4096
#define II 1024
#define HH 1024
#define MTOT (BB * TT)          // 32768
#define NC 32                   // scan chunks
#define CL 128                  // chunk length (NC*CL == TT)

// Scratch (device globals; no allocation allowed)
__device__ float g_a[(size_t)MTOT * HH];   // a_t = sigmoid(-k)
__device__ float g_b[(size_t)MTOT * HH];   // b_t = sigmoid(k) * g(p)
__device__ float g_A [BB * NC * HH];       // chunk prod of a
__device__ float g_Bc[BB * NC * HH];       // chunk recurrence from 0
__device__ float g_carry[BB * NC * HH];    // carry into each chunk

// ---------------- packed f32x2 helpers ----------------
__device__ __forceinline__ void fma2(uint64_t& d, uint64_t a, uint64_t b) {
    asm("fma.rn.f32x2 %0, %1, %2, %0;" : "+l"(d) : "l"(a), "l"(b));
}
__device__ __forceinline__ uint64_t pack2(float x, float y) {
    uint64_t r;
    asm("mov.b64 %0, {%1, %2};" : "=l"(r) : "f"(x), "f"(y));
    return r;
}
__device__ __forceinline__ float2 unpack2(uint64_t v) {
    float2 r;
    asm("mov.b64 {%0, %1}, %2;" : "=f"(r.x), "=f"(r.y) : "l"(v));
    return r;
}

__device__ __forceinline__ float sigmoidf_fast(float x) {
    return 1.0f / (1.0f + __expf(-x));
}
__device__ __forceinline__ float g_fn(float x) {
    // g(x) = x+0.5 for x>=0 else sigmoid(x)
    return (x >= 0.0f) ? (x + 0.5f) : (1.0f / (1.0f + __expf(-x)));
}

// ---------------- dual GEMM: k = x*Wz^T + bz, p = x*Wh^T + bh ----------------
// Tile: 128(M) x 64(N), 256 threads, micro 8x4 per thread, dual accumulators.
// Epilogue writes a = sigmoid(-k), b = sigmoid(k)*g(p) directly.
__global__ __launch_bounds__(256, 2)
void gemm_dual_kernel(const float* __restrict__ x,
                      const float* __restrict__ Wz,
                      const float* __restrict__ Wh,
                      const float* __restrict__ bz,
                      const float* __restrict__ bh) {
    __shared__ float sx [16][132];   // [k][m], padded (132 % 4 == 0 for float4)
    __shared__ float swz[16][68];    // [k][n]
    __shared__ float swh[16][68];

    const int tid = threadIdx.x;
    const int m0 = blockIdx.x * 128;
    const int n0 = blockIdx.y * 64;
    const int ty = tid >> 4;         // 0..15  -> 8 M-rows each
    const int tx = tid & 15;         // 0..15  -> 4 N-cols each

    uint64_t az[8][2], ap[8][2];
#pragma unroll
    for (int m = 0; m < 8; ++m) { az[m][0] = 0ull; az[m][1] = 0ull; ap[m][0] = 0ull; ap[m][1] = 0ull; }

    for (int k0 = 0; k0 < II; k0 += 16) {
        // x tile: rows m0..m0+127, cols k0..k0+15 -> sx[k][m]
#pragma unroll
        for (int r = 0; r < 2; ++r) {
            int f = tid * 2 + r;
            int row = f >> 2;
            int kq = (f & 3) * 4;
            float4 v = *(const float4*)(x + (size_t)(m0 + row) * II + k0 + kq);
            sx[kq + 0][row] = v.x; sx[kq + 1][row] = v.y;
            sx[kq + 2][row] = v.z; sx[kq + 3][row] = v.w;
        }
        // W tiles: rows n0..n0+63, cols k0..k0+15 -> swz/swh[k][n]
        {
            int row = tid >> 2;
            int kq = (tid & 3) * 4;
            float4 vz = *(const float4*)(Wz + (size_t)(n0 + row) * II + k0 + kq);
            swz[kq + 0][row] = vz.x; swz[kq + 1][row] = vz.y;
            swz[kq + 2][row] = vz.z; swz[kq + 3][row] = vz.w;
            float4 vh = *(const float4*)(Wh + (size_t)(n0 + row) * II + k0 + kq);
            swh[kq + 0][row] = vh.x; swh[kq + 1][row] = vh.y;
            swh[kq + 2][row] = vh.z; swh[kq + 3][row] = vh.w;
        }
        __syncthreads();

#pragma unroll
        for (int kk = 0; kk < 16; ++kk) {
            float4 xa = *(const float4*)&sx[kk][ty * 8];
            float4 xb = *(const float4*)&sx[kk][ty * 8 + 4];
            float4 wz4 = *(const float4*)&swz[kk][tx * 4];
            float4 wh4 = *(const float4*)&swh[kk][tx * 4];
            uint64_t wz01 = pack2(wz4.x, wz4.y), wz23 = pack2(wz4.z, wz4.w);
            uint64_t wh01 = pack2(wh4.x, wh4.y), wh23 = pack2(wh4.z, wh4.w);
            float xm[8] = {xa.x, xa.y, xa.z, xa.w, xb.x, xb.y, xb.z, xb.w};
#pragma unroll
            for (int m = 0; m < 8; ++m) {
                uint64_t xx = pack2(xm[m], xm[m]);
                fma2(az[m][0], xx, wz01);
                fma2(az[m][1], xx, wz23);
                fma2(ap[m][0], xx, wh01);
                fma2(ap[m][1], xx, wh23);
            }
        }
        __syncthreads();
    }

    // Epilogue: bias + activations -> g_a, g_b
    float bzv[4], bhv[4];
#pragma unroll
    for (int j = 0; j < 4; ++j) {
        bzv[j] = bz[n0 + tx * 4 + j];
        bhv[j] = bh[n0 + tx * 4 + j];
    }
#pragma unroll
    for (int m = 0; m < 8; ++m) {
        float2 z0 = unpack2(az[m][0]), z1 = unpack2(az[m][1]);
        float2 p0 = unpack2(ap[m][0]), p1 = unpack2(ap[m][1]);
        float kv[4] = {z0.x, z0.y, z1.x, z1.y};
        float pv[4] = {p0.x, p0.y, p1.x, p1.y};
        size_t row = (size_t)(m0 + ty * 8 + m);
        size_t off = row * HH + n0 + tx * 4;
#pragma unroll
        for (int j = 0; j < 4; ++j) {
            float kk = kv[j] + bzv[j];
            float pp = pv[j] + bhv[j];
            float a = 1.0f / (1.0f + __expf(kk));   // sigmoid(-k)
            float z = 1.0f - a;                     // sigmoid(k)
            g_a[off + j] = a;
            g_b[off + j] = z * g_fn(pp);
        }
    }
}

// ---------------- scan pass 1: per-chunk summaries ----------------
__global__ __launch_bounds__(256)
void scan_chunk_summary() {
    int idx = blockIdx.x * blockDim.x + threadIdx.x;   // (b, c, h)
    int h = idx & (HH - 1);
    int c = (idx >> 10) & (NC - 1);
    int b = idx >> 15;
    size_t base = ((size_t)(b * TT + c * CL)) * HH + h;

    float A = 1.0f, Bacc = 0.0f;
#pragma unroll 8
    for (int i = 0; i < CL; ++i) {
        float a = g_a[base + (size_t)i * HH];
        float bb = g_b[base + (size_t)i * HH];
        Bacc = fmaf(a, Bacc, bb);
        A *= a;
    }
    g_A[idx] = A;
    g_Bc[idx] = Bacc;
}

// ---------------- scan pass 2: combine chunks (sequential over NC) ----------------
__global__ __launch_bounds__(256)
void scan_chunk_combine(const float* __restrict__ h0) {
    int idx = blockIdx.x * blockDim.x + threadIdx.x;   // (b, h)
    int h = idx & (HH - 1);
    int b = idx >> 10;
    float carry = g_fn(h0[b * HH + h]);
#pragma unroll
    for (int c = 0; c < NC; ++c) {
        int s = (b * NC + c) * HH + h;
        g_carry[s] = carry;
        carry = fmaf(g_A[s], carry, g_Bc[s]);
    }
}

// ---------------- scan pass 3: apply carries, write output ----------------
__global__ __launch_bounds__(256)
void scan_apply(float* __restrict__ out) {
    int idx = blockIdx.x * blockDim.x + threadIdx.x;   // (b, c, h)
    int h = idx & (HH - 1);
    int c = (idx >> 10) & (NC - 1);
    int b = idx >> 15;
    size_t base = ((size_t)(b * TT + c * CL)) * HH + h;

    float hc = g_carry[(b * NC + c) * HH + h];
#pragma unroll 8
    for (int i = 0; i < CL; ++i) {
        float a = g_a[base + (size_t)i * HH];
        float bb = g_b[base + (size_t)i * HH];
        hc = fmaf(a, hc, bb);
        out[base + (size_t)i * HH] = hc;
    }
}

extern "C" void kernel_launch(void* const* d_in, const int* in_sizes, int n_in,
                              void* d_out, int out_size) {
    const float* x  = (const float*)d_in[0];
    const float* h0 = (const float*)d_in[1];
    const float* Wz = (const float*)d_in[2];
    const float* bz = (const float*)d_in[3];
    const float* Wh = (const float*)d_in[4];
    const float* bh = (const float*)d_in[5];
    float* out = (float*)d_out;

    dim3 ggrid(MTOT / 128, HH / 64);
    gemm_dual_kernel<<<ggrid, 256>>>(x, Wz, Wh, bz, bh);

    int nchains = BB * NC * HH;                  // 262144
    scan_chunk_summary<<<nchains / 256, 256>>>();
    scan_chunk_combine<<<(BB * HH) / 256, 256>>>(h0);
    scan_apply<<<nchains / 256, 256>>>(out);
}

// round 4
// speedup vs baseline: 1.5900x; 1.5900x over previous
#include <cuda_runtime.h>
#include <cuda_bf16.h>
#include <cstdint>

// Problem constants (fixed by setup_inputs)
#define BB 8
#define TT 4096
#define II 1024
#define HH 1024
#define MTOT (BB * TT)          // 32768
#define NC 32                   // scan chunks
#define CL 128                  // chunk length (NC*CL == TT)

#define KC 64                   // K-chunk (64 bf16 = 128B rows, SW128 swizzle)
#define NCHUNK (II / KC)        // 16
#define TILE_BYTES (128 * 128)  // 128 rows x 128B = 16KB
#define STAGE_BYTES (6 * TILE_BYTES)   // Ahi,Alo,Bzhi,Bzlo,Bhhi,Bhlo = 96KB
#define SMEM_TOTAL (2 * STAGE_BYTES)   // 192KB

// ---------------- scratch (device globals; no allocation allowed) ----------------
__device__ float g_a[(size_t)MTOT * HH];   // a_t = sigmoid(-k)
__device__ float g_b[(size_t)MTOT * HH];   // b_t = sigmoid(k)*g(p)
__device__ float g_A [BB * NC * HH];
__device__ float g_Bc[BB * NC * HH];
__device__ float g_carry[BB * NC * HH];
__device__ __nv_bfloat16 g_xhi[(size_t)MTOT * II];
__device__ __nv_bfloat16 g_xlo[(size_t)MTOT * II];
__device__ __nv_bfloat16 g_wzhi[HH * II];
__device__ __nv_bfloat16 g_wzlo[HH * II];
__device__ __nv_bfloat16 g_whhi[HH * II];
__device__ __nv_bfloat16 g_whlo[HH * II];

// ---------------- helpers ----------------
__device__ __forceinline__ uint32_t smem_u32(const void* p) {
    uint32_t a;
    asm("{ .reg .u64 t; cvta.to.shared.u64 t, %1; cvt.u32.u64 %0, t; }" : "=r"(a) : "l"(p));
    return a;
}
__device__ __forceinline__ void cp16(uint32_t saddr, const void* gaddr) {
    asm volatile("cp.async.cg.shared.global [%0], [%1], 16;" :: "r"(saddr), "l"(gaddr));
}
__device__ __forceinline__ void cp_commit() { asm volatile("cp.async.commit_group;" ::: "memory"); }
template <int N>
__device__ __forceinline__ void cp_wait() { asm volatile("cp.async.wait_group %0;" :: "n"(N) : "memory"); }

__device__ __forceinline__ void ldsm4(uint32_t (&r)[4], uint32_t addr) {
    asm volatile("ldmatrix.sync.aligned.m8n8.x4.shared.b16 {%0,%1,%2,%3}, [%4];"
        : "=r"(r[0]), "=r"(r[1]), "=r"(r[2]), "=r"(r[3]) : "r"(addr));
}
#define MMA16816(d, a, b0v, b1v) \
    asm volatile("mma.sync.aligned.m16n8k16.row.col.f32.bf16.bf16.f32 " \
        "{%0,%1,%2,%3}, {%4,%5,%6,%7}, {%8,%9}, {%0,%1,%2,%3};" \
        : "+f"((d)[0]), "+f"((d)[1]), "+f"((d)[2]), "+f"((d)[3]) \
        : "r"((a)[0]), "r"((a)[1]), "r"((a)[2]), "r"((a)[3]), "r"(b0v), "r"(b1v))

__device__ __forceinline__ uint32_t sw128(uint32_t off) { return off ^ ((off >> 3) & 0x70); }

// ---- pure fixed-latency-pipe exp / rcp (NO MUFU: MUFU would bottleneck at ~750us) ----
__device__ __forceinline__ float fexp(float x) {           // e^x, |x| < ~80, rel err ~2e-7
    float t = x * 1.4426950408889634f;
    float fi = t + 12582912.0f;                            // round-to-nearest via magic
    int i = __float_as_int(fi) - 0x4B400000;
    float f = t - (fi - 12582912.0f);                      // f in [-0.5, 0.5]
    float p = 1.5403530393381609e-4f;                      // 2^f Taylor deg-6
    p = fmaf(p, f, 1.3333558146428443e-3f);
    p = fmaf(p, f, 9.6181291076284772e-3f);
    p = fmaf(p, f, 5.5504108664821580e-2f);
    p = fmaf(p, f, 2.4022650695910072e-1f);
    p = fmaf(p, f, 6.9314718055994531e-1f);
    p = fmaf(p, f, 1.0f);
    return __int_as_float(__float_as_int(p) + (i << 23));
}
__device__ __forceinline__ float frcp(float d) {           // 1/d, d>0 normal, rel err ~4e-11
    float y = __int_as_float(0x7EF311C3 - __float_as_int(d));
    y = y * (2.0f - d * y);
    y = y * (2.0f - d * y);
    y = y * (2.0f - d * y);
    return y;
}
__device__ __forceinline__ float g_fn_scan(float x) {      // used in scan combine only (cheap)
    return (x >= 0.0f) ? (x + 0.5f) : frcp(1.0f + fexp(-x));
}

// ---------------- split fp32 -> bf16 hi/lo ----------------
__global__ __launch_bounds__(256)
void split_kernel(const float* __restrict__ in, __nv_bfloat16* __restrict__ hi, __nv_bfloat16* __restrict__ lo) {
    size_t i = ((size_t)blockIdx.x * blockDim.x + threadIdx.x) * 4;
    float4 v = *(const float4*)(in + i);
    float vs[4] = {v.x, v.y, v.z, v.w};
    __nv_bfloat16 hb[4], lb[4];
#pragma unroll
    for (int j = 0; j < 4; ++j) {
        hb[j] = __float2bfloat16(vs[j]);
        lb[j] = __float2bfloat16(vs[j] - __bfloat162float(hb[j]));
    }
    *(__nv_bfloat162*)(hi + i)     = __nv_bfloat162(hb[0], hb[1]);
    *(__nv_bfloat162*)(hi + i + 2) = __nv_bfloat162(hb[2], hb[3]);
    *(__nv_bfloat162*)(lo + i)     = __nv_bfloat162(lb[0], lb[1]);
    *(__nv_bfloat162*)(lo + i + 2) = __nv_bfloat162(lb[2], lb[3]);
}

// ---------------- chunk loader: 6 tiles of 128 rows x 128B, SW128-swizzled ----------------
__device__ __forceinline__ void load_chunk(uint32_t sbase, int m0, int n0, int k0, int tid) {
#pragma unroll
    for (int t = 0; t < 6; ++t) {
        const __nv_bfloat16* base;
        int r0;
        if      (t == 0) { base = g_xhi;  r0 = m0; }
        else if (t == 1) { base = g_xlo;  r0 = m0; }
        else if (t == 2) { base = g_wzhi; r0 = n0; }
        else if (t == 3) { base = g_wzlo; r0 = n0; }
        else if (t == 4) { base = g_whhi; r0 = n0; }
        else             { base = g_whlo; r0 = n0; }
#pragma unroll
        for (int s = 0; s < 4; ++s) {
            int i = tid + s * 256;        // 1024 chunks: 128 rows x 8 x 16B
            int r = i >> 3;
            int u = i & 7;
            const char* gp = (const char*)(base + (size_t)(r0 + r) * II + k0) + u * 16;
            uint32_t off = (uint32_t)(r * 128 + u * 16);
            cp16(sbase + (uint32_t)t * (uint32_t)TILE_BYTES + sw128(off), gp);
        }
    }
}

// ---------------- dual GEMM via legacy mma.sync (split-bf16, 3 terms) ----------------
__global__ __launch_bounds__(256, 1)
void gemm_mma_kernel(const float* __restrict__ bz, const float* __restrict__ bh) {
    extern __shared__ char smem[];
    const uint32_t sb = smem_u32(smem);
    const int tid = threadIdx.x;
    const int lane = tid & 31;
    const int wid = tid >> 5;
    const int g = lane >> 3, lr = lane & 7;
    const int wm = (wid >> 1) * 32;     // 4 warps along M
    const int wn = (wid & 1) * 64;      // 2 warps along N
    const int n0 = blockIdx.x * 128;    // H block (x-fast: all 8 n-blocks share A in a wave)
    const int m0 = blockIdx.y * 128;

    float acck[2][8][4], accp[2][8][4];
#pragma unroll
    for (int mt = 0; mt < 2; ++mt)
#pragma unroll
        for (int nt = 0; nt < 8; ++nt)
#pragma unroll
            for (int q = 0; q < 4; ++q) { acck[mt][nt][q] = 0.0f; accp[mt][nt][q] = 0.0f; }

    load_chunk(sb, m0, n0, 0, tid);
    cp_commit();

    for (int c = 0; c < NCHUNK; ++c) {
        if (c + 1 < NCHUNK) {
            load_chunk(sb + ((c + 1) & 1) * STAGE_BYTES, m0, n0, (c + 1) * KC, tid);
            cp_commit();
            cp_wait<1>();
        } else {
            cp_wait<0>();
        }
        __syncthreads();

        const uint32_t st = sb + (c & 1) * STAGE_BYTES;
        const uint32_t sAh = st, sAl = st + TILE_BYTES;
        const uint32_t sZh = st + 2 * TILE_BYTES, sZl = st + 3 * TILE_BYTES;
        const uint32_t sHh = st + 4 * TILE_BYTES, sHl = st + 5 * TILE_BYTES;

#pragma unroll
        for (int ks = 0; ks < 4; ++ks) {
            // A fragments (shared between k and p outputs)
            uint32_t ah[2][4], al[2][4];
#pragma unroll
            for (int mt = 0; mt < 2; ++mt) {
                uint32_t off = sw128((uint32_t)((wm + mt * 16 + (g & 1) * 8 + lr) * 128 + (2 * ks + (g >> 1)) * 16));
                ldsm4(ah[mt], sAh + off);
                ldsm4(al[mt], sAl + off);
            }
            uint32_t offb[4];
#pragma unroll
            for (int j = 0; j < 4; ++j)
                offb[j] = sw128((uint32_t)((wn + j * 16 + (g >> 1) * 8 + lr) * 128 + (2 * ks + (g & 1)) * 16));

            // ---- k output: Ahi*Bzhi + Ahi*Bzlo + Alo*Bzhi ----
            {
                uint32_t b0[4][4], b1[4][4];
#pragma unroll
                for (int j = 0; j < 4; ++j) { ldsm4(b0[j], sZh + offb[j]); ldsm4(b1[j], sZl + offb[j]); }
#pragma unroll
                for (int mt = 0; mt < 2; ++mt)
#pragma unroll
                    for (int nt = 0; nt < 8; ++nt) {
                        int j = nt >> 1, h = (nt & 1) * 2;
                        MMA16816(acck[mt][nt], ah[mt], b0[j][h], b0[j][h + 1]);
                        MMA16816(acck[mt][nt], al[mt], b0[j][h], b0[j][h + 1]);
                        MMA16816(acck[mt][nt], ah[mt], b1[j][h], b1[j][h + 1]);
                    }
            }
            // ---- p output: Ahi*Bhhi + Ahi*Bhlo + Alo*Bhhi ----
            {
                uint32_t b0[4][4], b1[4][4];
#pragma unroll
                for (int j = 0; j < 4; ++j) { ldsm4(b0[j], sHh + offb[j]); ldsm4(b1[j], sHl + offb[j]); }
#pragma unroll
                for (int mt = 0; mt < 2; ++mt)
#pragma unroll
                    for (int nt = 0; nt < 8; ++nt) {
                        int j = nt >> 1, h = (nt & 1) * 2;
                        MMA16816(accp[mt][nt], ah[mt], b0[j][h], b0[j][h + 1]);
                        MMA16816(accp[mt][nt], al[mt], b0[j][h], b0[j][h + 1]);
                        MMA16816(accp[mt][nt], ah[mt], b1[j][h], b1[j][h + 1]);
                    }
            }
        }
        __syncthreads();
    }

    // ---- epilogue: bias + activations (pure FFMA/ALU), direct stores ----
    float* sbz = (float*)smem;
    float* sbh = sbz + 128;
    if (tid < 128) {
        sbz[tid] = bz[n0 + tid];
        sbh[tid] = bh[n0 + tid];
    }
    __syncthreads();

#pragma unroll
    for (int mt = 0; mt < 2; ++mt)
#pragma unroll
        for (int nt = 0; nt < 8; ++nt) {
            int cc = wn + nt * 8 + (lane & 3) * 2;
            float bzv0 = sbz[cc], bzv1 = sbz[cc + 1];
            float bhv0 = sbh[cc], bhv1 = sbh[cc + 1];
#pragma unroll
            for (int h = 0; h < 2; ++h) {
                int r = m0 + wm + mt * 16 + (lane >> 2) + h * 8;
                float kv0 = acck[mt][nt][2 * h]     + bzv0;
                float kv1 = acck[mt][nt][2 * h + 1] + bzv1;
                float pv0 = accp[mt][nt][2 * h]     + bhv0;
                float pv1 = accp[mt][nt][2 * h + 1] + bhv1;

                float e0 = fexp(kv0), e1 = fexp(kv1);
                float r0 = frcp(1.0f + e0), r1 = frcp(1.0f + e1);
                float a0 = r0, a1 = r1;                 // sigmoid(-k)
                float z0 = e0 * r0, z1 = e1 * r1;       // sigmoid(k)
                float em0 = fexp(-pv0), em1 = fexp(-pv1);
                float gs0 = frcp(1.0f + em0), gs1 = frcp(1.0f + em1);
                float gg0 = (pv0 >= 0.0f) ? (pv0 + 0.5f) : gs0;
                float gg1 = (pv1 >= 0.0f) ? (pv1 + 0.5f) : gs1;

                size_t off = (size_t)r * HH + n0 + cc;
                *(float2*)(g_a + off) = make_float2(a0, a1);
                *(float2*)(g_b + off) = make_float2(z0 * gg0, z1 * gg1);
            }
        }
}

// ---------------- scan pass 1: per-chunk summaries ----------------
__global__ __launch_bounds__(256)
void scan_chunk_summary() {
    int idx = blockIdx.x * blockDim.x + threadIdx.x;   // (b, c, h)
    int h = idx & (HH - 1);
    int c = (idx >> 10) & (NC - 1);
    int b = idx >> 15;
    size_t base = ((size_t)(b * TT + c * CL)) * HH + h;
    float A = 1.0f, Bacc = 0.0f;
#pragma unroll 8
    for (int i = 0; i < CL; ++i) {
        float a = g_a[base + (size_t)i * HH];
        float bb = g_b[base + (size_t)i * HH];
        Bacc = fmaf(a, Bacc, bb);
        A *= a;
    }
    g_A[idx] = A;
    g_Bc[idx] = Bacc;
}

// ---------------- scan pass 2: combine chunks ----------------
__global__ __launch_bounds__(256)
void scan_chunk_combine(const float* __restrict__ h0) {
    int idx = blockIdx.x * blockDim.x + threadIdx.x;   // (b, h)
    int h = idx & (HH - 1);
    int b = idx >> 10;
    float carry = g_fn_scan(h0[b * HH + h]);
#pragma unroll
    for (int c = 0; c < NC; ++c) {
        int s = (b * NC + c) * HH + h;
        g_carry[s] = carry;
        carry = fmaf(g_A[s], carry, g_Bc[s]);
    }
}

// ---------------- scan pass 3: apply carries, write output ----------------
__global__ __launch_bounds__(256)
void scan_apply(float* __restrict__ out) {
    int idx = blockIdx.x * blockDim.x + threadIdx.x;   // (b, c, h)
    int h = idx & (HH - 1);
    int c = (idx >> 10) & (NC - 1);
    int b = idx >> 15;
    size_t base = ((size_t)(b * TT + c * CL)) * HH + h;
    float hc = g_carry[(b * NC + c) * HH + h];
#pragma unroll 8
    for (int i = 0; i < CL; ++i) {
        float a = g_a[base + (size_t)i * HH];
        float bb = g_b[base + (size_t)i * HH];
        hc = fmaf(a, hc, bb);
        out[base + (size_t)i * HH] = hc;
    }
}

extern "C" void kernel_launch(void* const* d_in, const int* in_sizes, int n_in,
                              void* d_out, int out_size) {
    const float* x  = (const float*)d_in[0];
    const float* h0 = (const float*)d_in[1];
    const float* Wz = (const float*)d_in[2];
    const float* bz = (const float*)d_in[3];
    const float* Wh = (const float*)d_in[4];
    const float* bh = (const float*)d_in[5];
    float* out = (float*)d_out;

    __nv_bfloat16 *xhi, *xlo, *wzhi, *wzlo, *whhi, *whlo;
    cudaGetSymbolAddress((void**)&xhi,  g_xhi);
    cudaGetSymbolAddress((void**)&xlo,  g_xlo);
    cudaGetSymbolAddress((void**)&wzhi, g_wzhi);
    cudaGetSymbolAddress((void**)&wzlo, g_wzlo);
    cudaGetSymbolAddress((void**)&whhi, g_whhi);
    cudaGetSymbolAddress((void**)&whlo, g_whlo);

    split_kernel<<<(int)(((size_t)MTOT * II) / 1024), 256>>>(x,  xhi,  xlo);
    split_kernel<<<(HH * II) / 1024, 256>>>(Wz, wzhi, wzlo);
    split_kernel<<<(HH * II) / 1024, 256>>>(Wh, whhi, whlo);

    cudaFuncSetAttribute(gemm_mma_kernel, cudaFuncAttributeMaxDynamicSharedMemorySize, SMEM_TOTAL);
    dim3 ggrid(HH / 128, MTOT / 128);   // x = n-block (8), y = m-block (256): A-reuse friendly
    gemm_mma_kernel<<<ggrid, 256, SMEM_TOTAL>>>(bz, bh);

    int nchains = BB * NC * HH;
    scan_chunk_summary<<<nchains / 256, 256>>>();
    scan_chunk_combine<<<(BB * HH) / 256, 256>>>(h0);
    scan_apply<<<nchains / 256, 256>>>(out);
}

// round 6
// speedup vs baseline: 3.2097x; 2.0187x over previous
#include <cuda_runtime.h>
#include <cuda_fp16.h>
#include <cstdint>

// Problem constants (fixed by setup_inputs)
#define BB 8
#define TT 4096
#define II 1024
#define HH 1024
#define MTOT (BB * TT)          // 32768
#define NC 32                   // scan chunks
#define CL 128                  // chunk length (NC*CL == TT)

#define KC 64                   // K-chunk (64 fp16 = 128B rows, SW128 swizzle)
#define NCHUNK (II / KC)        // 16
#define TILE_BYTES (128 * 128)  // 128 rows x 128B = 16KB
#define STAGE_BYTES (4 * TILE_BYTES)   // xh, xl, Wzh, Whh = 64KB
#define NSTAGE 3
#define SMEM_TOTAL (NSTAGE * STAGE_BYTES)   // 192KB

// ---------------- scratch (device globals; no allocation allowed) ----------------
__device__ float g_a[(size_t)MTOT * HH];   // a_t = sigmoid(-k)
__device__ float g_b[(size_t)MTOT * HH];   // b_t = sigmoid(k)*g(p)
__device__ float g_A [BB * NC * HH];
__device__ float g_Bc[BB * NC * HH];
__device__ float g_carry[BB * NC * HH];
__device__ __half g_xhi[(size_t)MTOT * II];
__device__ __half g_xlo[(size_t)MTOT * II];
__device__ __half g_wz[HH * II];
__device__ __half g_wh[HH * II];

// ---------------- helpers ----------------
__device__ __forceinline__ uint32_t smem_u32(const void* p) {
    uint32_t a;
    asm("{ .reg .u64 t; cvta.to.shared.u64 t, %1; cvt.u32.u64 %0, t; }" : "=r"(a) : "l"(p));
    return a;
}
__device__ __forceinline__ void cp16(uint32_t saddr, const void* gaddr) {
    asm volatile("cp.async.cg.shared.global [%0], [%1], 16;" :: "r"(saddr), "l"(gaddr));
}
__device__ __forceinline__ void cp_commit() { asm volatile("cp.async.commit_group;" ::: "memory"); }
template <int N>
__device__ __forceinline__ void cp_wait() { asm volatile("cp.async.wait_group %0;" :: "n"(N) : "memory"); }

__device__ __forceinline__ void ldsm4(uint32_t (&r)[4], uint32_t addr) {
    asm volatile("ldmatrix.sync.aligned.m8n8.x4.shared.b16 {%0,%1,%2,%3}, [%4];"
        : "=r"(r[0]), "=r"(r[1]), "=r"(r[2]), "=r"(r[3]) : "r"(addr));
}
#define MMA16816(d, a, b0v, b1v) \
    asm volatile("mma.sync.aligned.m16n8k16.row.col.f32.f16.f16.f32 " \
        "{%0,%1,%2,%3}, {%4,%5,%6,%7}, {%8,%9}, {%0,%1,%2,%3};" \
        : "+f"((d)[0]), "+f"((d)[1]), "+f"((d)[2]), "+f"((d)[3]) \
        : "r"((a)[0]), "r"((a)[1]), "r"((a)[2]), "r"((a)[3]), "r"(b0v), "r"(b1v))

__device__ __forceinline__ uint32_t sw128(uint32_t off) { return off ^ ((off >> 3) & 0x70); }

// ---- pure fixed-latency-pipe exp / rcp (keep MUFU idle) ----
__device__ __forceinline__ float fexp(float x) {           // e^x, rel err ~2e-7
    float t = x * 1.4426950408889634f;
    float fi = t + 12582912.0f;
    int i = __float_as_int(fi) - 0x4B400000;
    float f = t - (fi - 12582912.0f);
    float p = 1.5403530393381609e-4f;
    p = fmaf(p, f, 1.3333558146428443e-3f);
    p = fmaf(p, f, 9.6181291076284772e-3f);
    p = fmaf(p, f, 5.5504108664821580e-2f);
    p = fmaf(p, f, 2.4022650695910072e-1f);
    p = fmaf(p, f, 6.9314718055994531e-1f);
    p = fmaf(p, f, 1.0f);
    return __int_as_float(__float_as_int(p) + (i << 23));
}
__device__ __forceinline__ float frcp(float d) {           // 1/d, d>0 normal
    float y = __int_as_float(0x7EF311C3 - __float_as_int(d));
    y = y * (2.0f - d * y);
    y = y * (2.0f - d * y);
    y = y * (2.0f - d * y);
    return y;
}
__device__ __forceinline__ float g_fn_scan(float x) {
    return (x >= 0.0f) ? (x + 0.5f) : frcp(1.0f + fexp(-x));
}

// ---------------- split fp32 -> fp16 hi/lo (x) ----------------
__global__ __launch_bounds__(256)
void split_x_kernel(const float* __restrict__ in, __half* __restrict__ hi, __half* __restrict__ lo) {
    size_t i = ((size_t)blockIdx.x * blockDim.x + threadIdx.x) * 4;
    float4 v = *(const float4*)(in + i);
    float vs[4] = {v.x, v.y, v.z, v.w};
    __half hb[4], lb[4];
#pragma unroll
    for (int j = 0; j < 4; ++j) {
        hb[j] = __float2half(vs[j]);
        lb[j] = __float2half(vs[j] - __half2float(hb[j]));
    }
    *(__half2*)(hi + i)     = __half2(hb[0], hb[1]);
    *(__half2*)(hi + i + 2) = __half2(hb[2], hb[3]);
    *(__half2*)(lo + i)     = __half2(lb[0], lb[1]);
    *(__half2*)(lo + i + 2) = __half2(lb[2], lb[3]);
}

// ---------------- convert fp32 -> fp16 (weights) ----------------
__global__ __launch_bounds__(256)
void cvt_w_kernel(const float* __restrict__ in, __half* __restrict__ out) {
    size_t i = ((size_t)blockIdx.x * blockDim.x + threadIdx.x) * 4;
    float4 v = *(const float4*)(in + i);
    *(__half2*)(out + i)     = __half2(__float2half(v.x), __float2half(v.y));
    *(__half2*)(out + i + 2) = __half2(__float2half(v.z), __float2half(v.w));
}

// ---------------- chunk loader: 4 tiles of 128 rows x 128B, SW128-swizzled ----------------
__device__ __forceinline__ void load_chunk(uint32_t sbase, int m0, int n0, int k0, int tid) {
#pragma unroll
    for (int t = 0; t < 4; ++t) {
        const __half* base;
        int r0;
        if      (t == 0) { base = g_xhi; r0 = m0; }
        else if (t == 1) { base = g_xlo; r0 = m0; }
        else if (t == 2) { base = g_wz;  r0 = n0; }
        else             { base = g_wh;  r0 = n0; }
#pragma unroll
        for (int s = 0; s < 4; ++s) {
            int i = tid + s * 256;        // 1024 chunks: 128 rows x 8 x 16B
            int r = i >> 3;
            int u = i & 7;
            const char* gp = (const char*)(base + (size_t)(r0 + r) * II + k0) + u * 16;
            uint32_t off = (uint32_t)(r * 128 + u * 16);
            cp16(sbase + (uint32_t)t * (uint32_t)TILE_BYTES + sw128(off), gp);
        }
    }
}

// ---------------- dual GEMM via mma.sync (fp16 2-term: (xh+xl)*W) ----------------
__global__ __launch_bounds__(256, 1)
void gemm_mma_kernel(const float* __restrict__ bz, const float* __restrict__ bh) {
    extern __shared__ char smem[];
    const uint32_t sb = smem_u32(smem);
    const int tid = threadIdx.x;
    const int lane = tid & 31;
    const int wid = tid >> 5;
    const int g = lane >> 3, lr = lane & 7;
    const int wm = (wid >> 1) * 32;     // 4 warps along M
    const int wn = (wid & 1) * 64;      // 2 warps along N
    const int n0 = blockIdx.x * 128;    // H block (x-fast: wave shares A tiles)
    const int m0 = blockIdx.y * 128;

    float acck[2][8][4], accp[2][8][4];
#pragma unroll
    for (int mt = 0; mt < 2; ++mt)
#pragma unroll
        for (int nt = 0; nt < 8; ++nt)
#pragma unroll
            for (int q = 0; q < 4; ++q) { acck[mt][nt][q] = 0.0f; accp[mt][nt][q] = 0.0f; }

    load_chunk(sb, m0, n0, 0, tid);
    cp_commit();
    load_chunk(sb + STAGE_BYTES, m0, n0, KC, tid);
    cp_commit();

    for (int c = 0; c < NCHUNK; ++c) {
        if (c + 2 < NCHUNK) {
            load_chunk(sb + ((c + 2) % NSTAGE) * STAGE_BYTES, m0, n0, (c + 2) * KC, tid);
            cp_commit();
            cp_wait<2>();
        } else if (c + 1 < NCHUNK) {
            cp_wait<1>();
        } else {
            cp_wait<0>();
        }
        __syncthreads();

        const uint32_t st = sb + (c % NSTAGE) * STAGE_BYTES;
        const uint32_t sAh = st, sAl = st + TILE_BYTES;
        const uint32_t sZ = st + 2 * TILE_BYTES, sH = st + 3 * TILE_BYTES;

#pragma unroll
        for (int ks = 0; ks < 4; ++ks) {
            // A fragments (shared between k and p outputs)
            uint32_t ah[2][4], al[2][4];
#pragma unroll
            for (int mt = 0; mt < 2; ++mt) {
                uint32_t off = sw128((uint32_t)((wm + mt * 16 + (g & 1) * 8 + lr) * 128 + (2 * ks + (g >> 1)) * 16));
                ldsm4(ah[mt], sAh + off);
                ldsm4(al[mt], sAl + off);
            }
            uint32_t bzf[4][4], bhf[4][4];
#pragma unroll
            for (int j = 0; j < 4; ++j) {
                uint32_t off = sw128((uint32_t)((wn + j * 16 + (g >> 1) * 8 + lr) * 128 + (2 * ks + (g & 1)) * 16));
                ldsm4(bzf[j], sZ + off);
                ldsm4(bhf[j], sH + off);
            }
#pragma unroll
            for (int mt = 0; mt < 2; ++mt)
#pragma unroll
                for (int nt = 0; nt < 8; ++nt) {
                    int j = nt >> 1, h = (nt & 1) * 2;
                    MMA16816(acck[mt][nt], ah[mt], bzf[j][h], bzf[j][h + 1]);
                    MMA16816(acck[mt][nt], al[mt], bzf[j][h], bzf[j][h + 1]);
                    MMA16816(accp[mt][nt], ah[mt], bhf[j][h], bhf[j][h + 1]);
                    MMA16816(accp[mt][nt], al[mt], bhf[j][h], bhf[j][h + 1]);
                }
        }
        __syncthreads();
    }

    // ---- epilogue: bias + activations (pure FFMA/ALU), direct stores ----
    float* sbz = (float*)smem;
    float* sbh = sbz + 128;
    if (tid < 128) {
        sbz[tid] = bz[n0 + tid];
        sbh[tid] = bh[n0 + tid];
    }
    __syncthreads();

#pragma unroll
    for (int mt = 0; mt < 2; ++mt)
#pragma unroll
        for (int nt = 0; nt < 8; ++nt) {
            int cc = wn + nt * 8 + (lane & 3) * 2;
            float bzv0 = sbz[cc], bzv1 = sbz[cc + 1];
            float bhv0 = sbh[cc], bhv1 = sbh[cc + 1];
#pragma unroll
            for (int h = 0; h < 2; ++h) {
                int r = m0 + wm + mt * 16 + (lane >> 2) + h * 8;
                float kv0 = acck[mt][nt][2 * h]     + bzv0;
                float kv1 = acck[mt][nt][2 * h + 1] + bzv1;
                float pv0 = accp[mt][nt][2 * h]     + bhv0;
                float pv1 = accp[mt][nt][2 * h + 1] + bhv1;

                float e0 = fexp(kv0), e1 = fexp(kv1);
                float r0 = frcp(1.0f + e0), r1 = frcp(1.0f + e1);
                float a0 = r0, a1 = r1;                 // sigmoid(-k)
                float z0 = e0 * r0, z1 = e1 * r1;       // sigmoid(k)
                float em0 = fexp(-pv0), em1 = fexp(-pv1);
                float gs0 = frcp(1.0f + em0), gs1 = frcp(1.0f + em1);
                float gg0 = (pv0 >= 0.0f) ? (pv0 + 0.5f) : gs0;
                float gg1 = (pv1 >= 0.0f) ? (pv1 + 0.5f) : gs1;

                size_t off = (size_t)r * HH + n0 + cc;
                *(float2*)(g_a + off) = make_float2(a0, a1);
                *(float2*)(g_b + off) = make_float2(z0 * gg0, z1 * gg1);
            }
        }
}

// ---------------- scan pass 1: per-chunk summaries ----------------
__global__ __launch_bounds__(256)
void scan_chunk_summary() {
    int idx = blockIdx.x * blockDim.x + threadIdx.x;   // (b, c, h)
    int h = idx & (HH - 1);
    int c = (idx >> 10) & (NC - 1);
    int b = idx >> 15;
    size_t base = ((size_t)(b * TT + c * CL)) * HH + h;
    float A = 1.0f, Bacc = 0.0f;
#pragma unroll 8
    for (int i = 0; i < CL; ++i) {
        float a = g_a[base + (size_t)i * HH];
        float bb = g_b[base + (size_t)i * HH];
        Bacc = fmaf(a, Bacc, bb);
        A *= a;
    }
    g_A[idx] = A;
    g_Bc[idx] = Bacc;
}

// ---------------- scan pass 2: combine chunks ----------------
__global__ __launch_bounds__(256)
void scan_chunk_combine(const float* __restrict__ h0) {
    int idx = blockIdx.x * blockDim.x + threadIdx.x;   // (b, h)
    int h = idx & (HH - 1);
    int b = idx >> 10;
    float carry = g_fn_scan(h0[b * HH + h]);
#pragma unroll
    for (int c = 0; c < NC; ++c) {
        int s = (b * NC + c) * HH + h;
        g_carry[s] = carry;
        carry = fmaf(g_A[s], carry, g_Bc[s]);
    }
}

// ---------------- scan pass 3: apply carries, write output ----------------
__global__ __launch_bounds__(256)
void scan_apply(float* __restrict__ out) {
    int idx = blockIdx.x * blockDim.x + threadIdx.x;   // (b, c, h)
    int h = idx & (HH - 1);
    int c = (idx >> 10) & (NC - 1);
    int b = idx >> 15;
    size_t base = ((size_t)(b * TT + c * CL)) * HH + h;
    float hc = g_carry[(b * NC + c) * HH + h];
#pragma unroll 8
    for (int i = 0; i < CL; ++i) {
        float a = g_a[base + (size_t)i * HH];
        float bb = g_b[base + (size_t)i * HH];
        hc = fmaf(a, hc, bb);
        out[base + (size_t)i * HH] = hc;
    }
}

extern "C" void kernel_launch(void* const* d_in, const int* in_sizes, int n_in,
                              void* d_out, int out_size) {
    const float* x  = (const float*)d_in[0];
    const float* h0 = (const float*)d_in[1];
    const float* Wz = (const float*)d_in[2];
    const float* bz = (const float*)d_in[3];
    const float* Wh = (const float*)d_in[4];
    const float* bh = (const float*)d_in[5];
    float* out = (float*)d_out;

    __half *xhi, *xlo, *wz, *wh;
    cudaGetSymbolAddress((void**)&xhi, g_xhi);
    cudaGetSymbolAddress((void**)&xlo, g_xlo);
    cudaGetSymbolAddress((void**)&wz,  g_wz);
    cudaGetSymbolAddress((void**)&wh,  g_wh);

    split_x_kernel<<<(int)(((size_t)MTOT * II) / 1024), 256>>>(x, xhi, xlo);
    cvt_w_kernel<<<(HH * II) / 1024, 256>>>(Wz, wz);
    cvt_w_kernel<<<(HH * II) / 1024, 256>>>(Wh, wh);

    cudaFuncSetAttribute(gemm_mma_kernel, cudaFuncAttributeMaxDynamicSharedMemorySize, SMEM_TOTAL);
    dim3 ggrid(HH / 128, MTOT / 128);   // x = n-block (8), y = m-block (256)
    gemm_mma_kernel<<<ggrid, 256, SMEM_TOTAL>>>(bz, bh);

    int nchains = BB * NC * HH;
    scan_chunk_summary<<<nchains / 256, 256>>>();
    scan_chunk_combine<<<(BB * HH) / 256, 256>>>(h0);
    scan_apply<<<nchains / 256, 256>>>(out);
}

// round 8
// speedup vs baseline: 4.7548x; 1.4814x over previous
#include <cuda_runtime.h>
#include <cuda_fp16.h>
#include <cstdint>

// Problem constants (fixed by setup_inputs)
#define BB 8
#define TT 4096
#define II 1024
#define HH 1024
#define MTOT (BB * TT)          // 32768
#define NC 32                   // scan chunks
#define CL 128                  // chunk length (NC*CL == TT)

#define KC 64                   // K-chunk (64 fp16 = 128B rows, SW128 swizzle)
#define NCHUNK (II / KC)        // 16
#define TILE_BYTES (128 * 128)  // 128 rows x 128B = 16KB
#define STAGE_BYTES (3 * TILE_BYTES)   // x, Wz, Wh = 48KB
#define NSTAGE 4
#define SMEM_TOTAL (NSTAGE * STAGE_BYTES)   // 192KB

// ---------------- scratch (device globals; no allocation allowed) ----------------
__device__ float g_a[(size_t)MTOT * HH];   // a_t = sigmoid(-k)
__device__ float g_b[(size_t)MTOT * HH];   // b_t = sigmoid(k)*g(p)
__device__ float g_A [BB * NC * HH];
__device__ float g_Bc[BB * NC * HH];
__device__ float g_carry[BB * NC * HH];
__device__ __half g_x16[(size_t)MTOT * II];
__device__ __half g_wz[HH * II];
__device__ __half g_wh[HH * II];

// ---------------- helpers ----------------
__device__ __forceinline__ uint32_t smem_u32(const void* p) {
    uint32_t a;
    asm("{ .reg .u64 t; cvta.to.shared.u64 t, %1; cvt.u32.u64 %0, t; }" : "=r"(a) : "l"(p));
    return a;
}
__device__ __forceinline__ void cp16(uint32_t saddr, const void* gaddr) {
    asm volatile("cp.async.cg.shared.global [%0], [%1], 16;" :: "r"(saddr), "l"(gaddr));
}
__device__ __forceinline__ void cp_commit() { asm volatile("cp.async.commit_group;" ::: "memory"); }
template <int N>
__device__ __forceinline__ void cp_wait() { asm volatile("cp.async.wait_group %0;" :: "n"(N) : "memory"); }

__device__ __forceinline__ void ldsm4(uint32_t (&r)[4], uint32_t addr) {
    asm volatile("ldmatrix.sync.aligned.m8n8.x4.shared.b16 {%0,%1,%2,%3}, [%4];"
        : "=r"(r[0]), "=r"(r[1]), "=r"(r[2]), "=r"(r[3]) : "r"(addr));
}
#define MMA16816(d, a, b0v, b1v) \
    asm volatile("mma.sync.aligned.m16n8k16.row.col.f32.f16.f16.f32 " \
        "{%0,%1,%2,%3}, {%4,%5,%6,%7}, {%8,%9}, {%0,%1,%2,%3};" \
        : "+f"((d)[0]), "+f"((d)[1]), "+f"((d)[2]), "+f"((d)[3]) \
        : "r"((a)[0]), "r"((a)[1]), "r"((a)[2]), "r"((a)[3]), "r"(b0v), "r"(b1v))

__device__ __forceinline__ uint32_t sw128(uint32_t off) { return off ^ ((off >> 3) & 0x70); }

// ---- pure fixed-latency-pipe exp / rcp (keep MUFU idle) ----
__device__ __forceinline__ float fexp(float x) {           // e^x, rel err ~2e-7
    float t = x * 1.4426950408889634f;
    float fi = t + 12582912.0f;
    int i = __float_as_int(fi) - 0x4B400000;
    float f = t - (fi - 12582912.0f);
    float p = 1.5403530393381609e-4f;
    p = fmaf(p, f, 1.3333558146428443e-3f);
    p = fmaf(p, f, 9.6181291076284772e-3f);
    p = fmaf(p, f, 5.5504108664821580e-2f);
    p = fmaf(p, f, 2.4022650695910072e-1f);
    p = fmaf(p, f, 6.9314718055994531e-1f);
    p = fmaf(p, f, 1.0f);
    return __int_as_float(__float_as_int(p) + (i << 23));
}
__device__ __forceinline__ float frcp(float d) {           // 1/d, d>0 normal
    float y = __int_as_float(0x7EF311C3 - __float_as_int(d));
    y = y * (2.0f - d * y);
    y = y * (2.0f - d * y);
    y = y * (2.0f - d * y);
    return y;
}
__device__ __forceinline__ float g_fn_scan(float x) {
    return (x >= 0.0f) ? (x + 0.5f) : frcp(1.0f + fexp(-x));
}

// ---------------- convert fp32 -> fp16 ----------------
__global__ __launch_bounds__(256)
void cvt_kernel(const float* __restrict__ in, __half* __restrict__ out) {
    size_t i = ((size_t)blockIdx.x * blockDim.x + threadIdx.x) * 4;
    float4 v = *(const float4*)(in + i);
    *(__half2*)(out + i)     = __half2(__float2half(v.x), __float2half(v.y));
    *(__half2*)(out + i + 2) = __half2(__float2half(v.z), __float2half(v.w));
}

// ---------------- chunk loader: 3 tiles of 128 rows x 128B, SW128-swizzled ----------------
__device__ __forceinline__ void load_chunk(uint32_t sbase, int m0, int n0, int k0, int tid) {
#pragma unroll
    for (int t = 0; t < 3; ++t) {
        const __half* base;
        int r0;
        if      (t == 0) { base = g_x16; r0 = m0; }
        else if (t == 1) { base = g_wz;  r0 = n0; }
        else             { base = g_wh;  r0 = n0; }
#pragma unroll
        for (int s = 0; s < 4; ++s) {
            int i = tid + s * 256;        // 1024 chunks: 128 rows x 8 x 16B
            int r = i >> 3;
            int u = i & 7;
            const char* gp = (const char*)(base + (size_t)(r0 + r) * II + k0) + u * 16;
            uint32_t off = (uint32_t)(r * 128 + u * 16);
            cp16(sbase + (uint32_t)t * (uint32_t)TILE_BYTES + sw128(off), gp);
        }
    }
}

// ---------------- dual GEMM via mma.sync (fp16 1-term) ----------------
__global__ __launch_bounds__(256, 1)
void gemm_mma_kernel(const float* __restrict__ bz, const float* __restrict__ bh) {
    extern __shared__ char smem[];
    const uint32_t sb = smem_u32(smem);
    const int tid = threadIdx.x;
    const int lane = tid & 31;
    const int wid = tid >> 5;
    const int g = lane >> 3, lr = lane & 7;
    const int wm = (wid >> 1) * 32;     // 4 warps along M
    const int wn = (wid & 1) * 64;      // 2 warps along N
    const int n0 = blockIdx.x * 128;    // H block (x-fast: wave shares A tiles)
    const int m0 = blockIdx.y * 128;

    float acck[2][8][4], accp[2][8][4];
#pragma unroll
    for (int mt = 0; mt < 2; ++mt)
#pragma unroll
        for (int nt = 0; nt < 8; ++nt)
#pragma unroll
            for (int q = 0; q < 4; ++q) { acck[mt][nt][q] = 0.0f; accp[mt][nt][q] = 0.0f; }

    load_chunk(sb, m0, n0, 0, tid);
    cp_commit();
    load_chunk(sb + STAGE_BYTES, m0, n0, KC, tid);
    cp_commit();
    load_chunk(sb + 2 * STAGE_BYTES, m0, n0, 2 * KC, tid);
    cp_commit();

    for (int c = 0; c < NCHUNK; ++c) {
        if (c + 3 < NCHUNK) {
            load_chunk(sb + ((c + 3) % NSTAGE) * STAGE_BYTES, m0, n0, (c + 3) * KC, tid);
            cp_commit();
            cp_wait<3>();
        } else if (c + 2 < NCHUNK) {
            cp_wait<2>();
        } else if (c + 1 < NCHUNK) {
            cp_wait<1>();
        } else {
            cp_wait<0>();
        }
        __syncthreads();

        const uint32_t st = sb + (c % NSTAGE) * STAGE_BYTES;
        const uint32_t sA = st;
        const uint32_t sZ = st + TILE_BYTES, sH = st + 2 * TILE_BYTES;

#pragma unroll
        for (int ks = 0; ks < 4; ++ks) {
            // A fragments (shared between k and p outputs)
            uint32_t af[2][4];
#pragma unroll
            for (int mt = 0; mt < 2; ++mt) {
                uint32_t off = sw128((uint32_t)((wm + mt * 16 + (g & 1) * 8 + lr) * 128 + (2 * ks + (g >> 1)) * 16));
                ldsm4(af[mt], sA + off);
            }
            uint32_t bzf[4][4], bhf[4][4];
#pragma unroll
            for (int j = 0; j < 4; ++j) {
                uint32_t off = sw128((uint32_t)((wn + j * 16 + (g >> 1) * 8 + lr) * 128 + (2 * ks + (g & 1)) * 16));
                ldsm4(bzf[j], sZ + off);
                ldsm4(bhf[j], sH + off);
            }
#pragma unroll
            for (int mt = 0; mt < 2; ++mt)
#pragma unroll
                for (int nt = 0; nt < 8; ++nt) {
                    int j = nt >> 1, h = (nt & 1) * 2;
                    MMA16816(acck[mt][nt], af[mt], bzf[j][h], bzf[j][h + 1]);
                    MMA16816(accp[mt][nt], af[mt], bhf[j][h], bhf[j][h + 1]);
                }
        }
        __syncthreads();
    }

    // ---- epilogue: bias + activations (pure FFMA/ALU), direct stores ----
    float* sbz = (float*)smem;
    float* sbh = sbz + 128;
    if (tid < 128) {
        sbz[tid] = bz[n0 + tid];
        sbh[tid] = bh[n0 + tid];
    }
    __syncthreads();

#pragma unroll
    for (int mt = 0; mt < 2; ++mt)
#pragma unroll
        for (int nt = 0; nt < 8; ++nt) {
            int cc = wn + nt * 8 + (lane & 3) * 2;
            float bzv0 = sbz[cc], bzv1 = sbz[cc + 1];
            float bhv0 = sbh[cc], bhv1 = sbh[cc + 1];
#pragma unroll
            for (int h = 0; h < 2; ++h) {
                int r = m0 + wm + mt * 16 + (lane >> 2) + h * 8;
                float kv0 = acck[mt][nt][2 * h]     + bzv0;
                float kv1 = acck[mt][nt][2 * h + 1] + bzv1;
                float pv0 = accp[mt][nt][2 * h]     + bhv0;
                float pv1 = accp[mt][nt][2 * h + 1] + bhv1;

                float e0 = fexp(kv0), e1 = fexp(kv1);
                float r0 = frcp(1.0f + e0), r1 = frcp(1.0f + e1);
                float a0 = r0, a1 = r1;                 // sigmoid(-k)
                float z0 = e0 * r0, z1 = e1 * r1;       // sigmoid(k)
                float em0 = fexp(-pv0), em1 = fexp(-pv1);
                float gs0 = frcp(1.0f + em0), gs1 = frcp(1.0f + em1);
                float gg0 = (pv0 >= 0.0f) ? (pv0 + 0.5f) : gs0;
                float gg1 = (pv1 >= 0.0f) ? (pv1 + 0.5f) : gs1;

                size_t off = (size_t)r * HH + n0 + cc;
                *(float2*)(g_a + off) = make_float2(a0, a1);
                *(float2*)(g_b + off) = make_float2(z0 * gg0, z1 * gg1);
            }
        }
}

// ---------------- scan pass 1: per-chunk summaries ----------------
__global__ __launch_bounds__(256)
void scan_chunk_summary() {
    int idx = blockIdx.x * blockDim.x + threadIdx.x;   // (b, c, h)
    int h = idx & (HH - 1);
    int c = (idx >> 10) & (NC - 1);
    int b = idx >> 15;
    size_t base = ((size_t)(b * TT + c * CL)) * HH + h;
    float A = 1.0f, Bacc = 0.0f;
#pragma unroll 8
    for (int i = 0; i < CL; ++i) {
        float a = g_a[base + (size_t)i * HH];
        float bb = g_b[base + (size_t)i * HH];
        Bacc = fmaf(a, Bacc, bb);
        A *= a;
    }
    g_A[idx] = A;
    g_Bc[idx] = Bacc;
}

// ---------------- scan pass 2: combine chunks ----------------
__global__ __launch_bounds__(256)
void scan_chunk_combine(const float* __restrict__ h0) {
    int idx = blockIdx.x * blockDim.x + threadIdx.x;   // (b, h)
    int h = idx & (HH - 1);
    int b = idx >> 10;
    float carry = g_fn_scan(h0[b * HH + h]);
#pragma unroll
    for (int c = 0; c < NC; ++c) {
        int s = (b * NC + c) * HH + h;
        g_carry[s] = carry;
        carry = fmaf(g_A[s], carry, g_Bc[s]);
    }
}

// ---------------- scan pass 3: apply carries, write output ----------------
__global__ __launch_bounds__(256)
void scan_apply(float* __restrict__ out) {
    int idx = blockIdx.x * blockDim.x + threadIdx.x;   // (b, c, h)
    int h = idx & (HH - 1);
    int c = (idx >> 10) & (NC - 1);
    int b = idx >> 15;
    size_t base = ((size_t)(b * TT + c * CL)) * HH + h;
    float hc = g_carry[(b * NC + c) * HH + h];
#pragma unroll 8
    for (int i = 0; i < CL; ++i) {
        float a = g_a[base + (size_t)i * HH];
        float bb = g_b[base + (size_t)i * HH];
        hc = fmaf(a, hc, bb);
        out[base + (size_t)i * HH] = hc;
    }
}

extern "C" void kernel_launch(void* const* d_in, const int* in_sizes, int n_in,
                              void* d_out, int out_size) {
    const float* x  = (const float*)d_in[0];
    const float* h0 = (const float*)d_in[1];
    const float* Wz = (const float*)d_in[2];
    const float* bz = (const float*)d_in[3];
    const float* Wh = (const float*)d_in[4];
    const float* bh = (const float*)d_in[5];
    float* out = (float*)d_out;

    __half *x16, *wz, *wh;
    cudaGetSymbolAddress((void**)&x16, g_x16);
    cudaGetSymbolAddress((void**)&wz,  g_wz);
    cudaGetSymbolAddress((void**)&wh,  g_wh);

    cvt_kernel<<<(int)(((size_t)MTOT * II) / 1024), 256>>>(x, x16);
    cvt_kernel<<<(HH * II) / 1024, 256>>>(Wz, wz);
    cvt_kernel<<<(HH * II) / 1024, 256>>>(Wh, wh);

    cudaFuncSetAttribute(gemm_mma_kernel, cudaFuncAttributeMaxDynamicSharedMemorySize, SMEM_TOTAL);
    dim3 ggrid(HH / 128, MTOT / 128);   // x = n-block (8), y = m-block (256)
    gemm_mma_kernel<<<ggrid, 256, SMEM_TOTAL>>>(bz, bh);

    int nchains = BB * NC * HH;
    scan_chunk_summary<<<nchains / 256, 256>>>();
    scan_chunk_combine<<<(BB * HH) / 256, 256>>>(h0);
    scan_apply<<<nchains / 256, 256>>>(out);
}

// round 10
// speedup vs baseline: 4.9837x; 1.0481x over previous
#include <cuda_runtime.h>
#include <cuda_fp16.h>
#include <cstdint>

// Problem constants (fixed by setup_inputs)
#define BB 8
#define TT 4096
#define II 1024
#define HH 1024
#define MTOT (BB * TT)          // 32768
#define NC 32                   // scan chunks
#define CL 128                  // chunk length (NC*CL == TT)

#define KC 128                  // K-chunk (two 64-col SW128 sub-tiles per tensor)
#define NCHUNK (II / KC)        // 8
#define SUB_BYTES (128 * 128)   // 128 rows x 128B = 16KB sub-tile
#define STAGE_BYTES (6 * SUB_BYTES)    // x0,x1,wz0,wz1,wh0,wh1 = 96KB
#define NSTAGE 2
#define SMEM_TOTAL (NSTAGE * STAGE_BYTES)   // 192KB

// ---------------- scratch (device globals; no allocation allowed) ----------------
__device__ float g_a[(size_t)MTOT * HH];   // a_t = sigmoid(-k)
__device__ float g_b[(size_t)MTOT * HH];   // b_t = sigmoid(k)*g(p)
__device__ float g_A [BB * NC * HH];
__device__ float g_Bc[BB * NC * HH];
__device__ float g_carry[BB * NC * HH];
__device__ __half g_x16[(size_t)MTOT * II];
__device__ __half g_wz[HH * II];
__device__ __half g_wh[HH * II];

// ---------------- helpers ----------------
__device__ __forceinline__ uint32_t smem_u32(const void* p) {
    uint32_t a;
    asm("{ .reg .u64 t; cvta.to.shared.u64 t, %1; cvt.u32.u64 %0, t; }" : "=r"(a) : "l"(p));
    return a;
}
__device__ __forceinline__ void cp16(uint32_t saddr, const void* gaddr) {
    asm volatile("cp.async.cg.shared.global [%0], [%1], 16;" :: "r"(saddr), "l"(gaddr));
}
__device__ __forceinline__ void cp_commit() { asm volatile("cp.async.commit_group;" ::: "memory"); }
template <int N>
__device__ __forceinline__ void cp_wait() { asm volatile("cp.async.wait_group %0;" :: "n"(N) : "memory"); }

__device__ __forceinline__ void ldsm4(uint32_t (&r)[4], uint32_t addr) {
    asm volatile("ldmatrix.sync.aligned.m8n8.x4.shared.b16 {%0,%1,%2,%3}, [%4];"
        : "=r"(r[0]), "=r"(r[1]), "=r"(r[2]), "=r"(r[3]) : "r"(addr));
}
#define MMA16816(d, a, b0v, b1v) \
    asm volatile("mma.sync.aligned.m16n8k16.row.col.f32.f16.f16.f32 " \
        "{%0,%1,%2,%3}, {%4,%5,%6,%7}, {%8,%9}, {%0,%1,%2,%3};" \
        : "+f"((d)[0]), "+f"((d)[1]), "+f"((d)[2]), "+f"((d)[3]) \
        : "r"((a)[0]), "r"((a)[1]), "r"((a)[2]), "r"((a)[3]), "r"(b0v), "r"(b1v))

__device__ __forceinline__ uint32_t sw128(uint32_t off) { return off ^ ((off >> 3) & 0x70); }

// ---- pure fixed-latency-pipe exp / rcp (keep MUFU idle) ----
__device__ __forceinline__ float fexp(float x) {           // e^x, rel err ~2e-7
    float t = x * 1.4426950408889634f;
    float fi = t + 12582912.0f;
    int i = __float_as_int(fi) - 0x4B400000;
    float f = t - (fi - 12582912.0f);
    float p = 1.5403530393381609e-4f;
    p = fmaf(p, f, 1.3333558146428443e-3f);
    p = fmaf(p, f, 9.6181291076284772e-3f);
    p = fmaf(p, f, 5.5504108664821580e-2f);
    p = fmaf(p, f, 2.4022650695910072e-1f);
    p = fmaf(p, f, 6.9314718055994531e-1f);
    p = fmaf(p, f, 1.0f);
    return __int_as_float(__float_as_int(p) + (i << 23));
}
__device__ __forceinline__ float frcp(float d) {           // 1/d, d>0 normal
    float y = __int_as_float(0x7EF311C3 - __float_as_int(d));
    y = y * (2.0f - d * y);
    y = y * (2.0f - d * y);
    y = y * (2.0f - d * y);
    return y;
}
__device__ __forceinline__ float g_fn_scan(float x) {
    return (x >= 0.0f) ? (x + 0.5f) : frcp(1.0f + fexp(-x));
}

// ---------------- convert fp32 -> fp16 ----------------
__global__ __launch_bounds__(256)
void cvt_kernel(const float* __restrict__ in, __half* __restrict__ out) {
    size_t i = ((size_t)blockIdx.x * blockDim.x + threadIdx.x) * 4;
    float4 v = *(const float4*)(in + i);
    *(__half2*)(out + i)     = __half2(__float2half(v.x), __float2half(v.y));
    *(__half2*)(out + i + 2) = __half2(__float2half(v.z), __float2half(v.w));
}

// ---------------- chunk loader: 6 sub-tiles (x/wz/wh x 2 k-halves), SW128 ----------------
__device__ __forceinline__ void load_chunk(uint32_t sbase, int m0, int n0, int k0, int tid) {
#pragma unroll
    for (int t = 0; t < 3; ++t) {
        const __half* base;
        int r0;
        if      (t == 0) { base = g_x16; r0 = m0; }
        else if (t == 1) { base = g_wz;  r0 = n0; }
        else             { base = g_wh;  r0 = n0; }
#pragma unroll
        for (int half = 0; half < 2; ++half) {
            uint32_t sub = sbase + (uint32_t)(t * 2 + half) * (uint32_t)SUB_BYTES;
            int kk = k0 + half * 64;
#pragma unroll
            for (int s = 0; s < 4; ++s) {
                int i = tid + s * 256;        // 1024 chunks: 128 rows x 8 x 16B
                int r = i >> 3;
                int u = i & 7;
                const char* gp = (const char*)(base + (size_t)(r0 + r) * II + kk) + u * 16;
                uint32_t off = (uint32_t)(r * 128 + u * 16);
                cp16(sub + sw128(off), gp);
            }
        }
    }
}

// ---------------- dual GEMM via mma.sync + fused chunk-summary epilogue ----------------
__global__ __launch_bounds__(256, 1)
void gemm_mma_kernel(const float* __restrict__ bz, const float* __restrict__ bh) {
    extern __shared__ char smem[];
    const uint32_t sb = smem_u32(smem);
    const int tid = threadIdx.x;
    const int lane = tid & 31;
    const int wid = tid >> 5;
    const int g = lane >> 3, lr = lane & 7;
    const int wm = (wid >> 1) * 32;     // 4 warps along M
    const int wn = (wid & 1) * 64;      // 2 warps along N
    const int n0 = blockIdx.x * 128;    // H block (x-fast: wave shares A tiles)
    const int m0 = blockIdx.y * 128;

    float acck[2][8][4], accp[2][8][4];
#pragma unroll
    for (int mt = 0; mt < 2; ++mt)
#pragma unroll
        for (int nt = 0; nt < 8; ++nt)
#pragma unroll
            for (int q = 0; q < 4; ++q) { acck[mt][nt][q] = 0.0f; accp[mt][nt][q] = 0.0f; }

    load_chunk(sb, m0, n0, 0, tid);
    cp_commit();

    for (int c = 0; c < NCHUNK; ++c) {
        cp_wait<0>();          // chunk c resident
        __syncthreads();       // everyone done with the other slot's MMAs
        if (c + 1 < NCHUNK) {  // prefetch c+1 into the other slot (overlaps MMA below)
            load_chunk(sb + ((c + 1) & 1) * STAGE_BYTES, m0, n0, (c + 1) * KC, tid);
            cp_commit();
        }

        const uint32_t st = sb + (c & 1) * STAGE_BYTES;

#pragma unroll
        for (int ks = 0; ks < 8; ++ks) {
            const int half = ks >> 2, ksl = ks & 3;
            const uint32_t sA = st + (uint32_t)(0 + half) * SUB_BYTES;
            const uint32_t sZ = st + (uint32_t)(2 + half) * SUB_BYTES;
            const uint32_t sH = st + (uint32_t)(4 + half) * SUB_BYTES;

            uint32_t af[2][4];
#pragma unroll
            for (int mt = 0; mt < 2; ++mt) {
                uint32_t off = sw128((uint32_t)((wm + mt * 16 + (g & 1) * 8 + lr) * 128 + (2 * ksl + (g >> 1)) * 16));
                ldsm4(af[mt], sA + off);
            }
            uint32_t bzf[4][4], bhf[4][4];
#pragma unroll
            for (int j = 0; j < 4; ++j) {
                uint32_t off = sw128((uint32_t)((wn + j * 16 + (g >> 1) * 8 + lr) * 128 + (2 * ksl + (g & 1)) * 16));
                ldsm4(bzf[j], sZ + off);
                ldsm4(bhf[j], sH + off);
            }
#pragma unroll
            for (int mt = 0; mt < 2; ++mt)
#pragma unroll
                for (int nt = 0; nt < 8; ++nt) {
                    int j = nt >> 1, h = (nt & 1) * 2;
                    MMA16816(acck[mt][nt], af[mt], bzf[j][h], bzf[j][h + 1]);
                    MMA16816(accp[mt][nt], af[mt], bhf[j][h], bhf[j][h + 1]);
                }
        }
    }
    __syncthreads();   // stages dead; smem becomes a/b planes

    // ---- epilogue: bias + activations -> smem planes [128][132] ----
    float* planeA = (float*)smem;             // a values, 128*132 floats
    float* planeB = planeA + 128 * 132;       // b values
    float* partA  = planeB + 128 * 132;       // 256 half-chain partials
    float* partB  = partA + 256;

#pragma unroll
    for (int mt = 0; mt < 2; ++mt)
#pragma unroll
        for (int nt = 0; nt < 8; ++nt) {
            int cc = wn + nt * 8 + (lane & 3) * 2;
            float bzv0 = bz[n0 + cc], bzv1 = bz[n0 + cc + 1];
            float bhv0 = bh[n0 + cc], bhv1 = bh[n0 + cc + 1];
#pragma unroll
            for (int h = 0; h < 2; ++h) {
                int r = wm + mt * 16 + (lane >> 2) + h * 8;   // local t-row 0..127
                float kv0 = acck[mt][nt][2 * h]     + bzv0;
                float kv1 = acck[mt][nt][2 * h + 1] + bzv1;
                float pv0 = accp[mt][nt][2 * h]     + bhv0;
                float pv1 = accp[mt][nt][2 * h + 1] + bhv1;

                float e0 = fexp(kv0), e1 = fexp(kv1);
                float r0 = frcp(1.0f + e0), r1 = frcp(1.0f + e1);
                float a0 = r0, a1 = r1;                 // sigmoid(-k)
                float z0 = e0 * r0, z1 = e1 * r1;       // sigmoid(k)
                float em0 = fexp(-pv0), em1 = fexp(-pv1);
                float gs0 = frcp(1.0f + em0), gs1 = frcp(1.0f + em1);
                float gg0 = (pv0 >= 0.0f) ? (pv0 + 0.5f) : gs0;
                float gg1 = (pv1 >= 0.0f) ? (pv1 + 0.5f) : gs1;

                *(float2*)(planeA + r * 132 + cc) = make_float2(a0, a1);
                *(float2*)(planeB + r * 132 + cc) = make_float2(z0 * gg0, z1 * gg1);
            }
        }
    __syncthreads();

    // ---- in-CTA chunk summary: 256 half-chains of 64 steps, then combine ----
    {
        const int h = tid & 127;
        const int half = tid >> 7;           // 0: t 0..63, 1: t 64..127
        float A = 1.0f, Bacc = 0.0f;
        const float* pa = planeA + (half * 64) * 132 + h;
        const float* pb = planeB + (half * 64) * 132 + h;
#pragma unroll 8
        for (int i = 0; i < 64; ++i) {
            float a = pa[i * 132];
            float bb = pb[i * 132];
            Bacc = fmaf(a, Bacc, bb);
            A *= a;
        }
        partA[tid] = A;
        partB[tid] = Bacc;
    }
    __syncthreads();
    if (tid < 128) {
        float A0 = partA[tid], B0 = partB[tid];
        float A1 = partA[128 + tid], B1 = partB[128 + tid];
        int b = m0 >> 12, c = (m0 >> 7) & (NC - 1);
        int idx = (b * NC + c) * HH + n0 + tid;
        g_A[idx]  = A0 * A1;
        g_Bc[idx] = fmaf(A1, B0, B1);
    }

    // ---- coalesced g_a / g_b stores from planes ----
#pragma unroll
    for (int pass = 0; pass < 4; ++pass) {
        int r = pass * 32 + (tid >> 3);
        size_t grow = (size_t)(m0 + r) * HH + n0;
#pragma unroll
        for (int q = 0; q < 4; ++q) {
            int c4 = q * 8 + (tid & 7);
            *(float4*)(g_a + grow + c4 * 4) = *(float4*)(planeA + r * 132 + c4 * 4);
            *(float4*)(g_b + grow + c4 * 4) = *(float4*)(planeB + r * 132 + c4 * 4);
        }
    }
}

// ---------------- scan pass 2: combine chunks ----------------
__global__ __launch_bounds__(256)
void scan_chunk_combine(const float* __restrict__ h0) {
    int idx = blockIdx.x * blockDim.x + threadIdx.x;   // (b, h)
    int h = idx & (HH - 1);
    int b = idx >> 10;
    float carry = g_fn_scan(h0[b * HH + h]);
#pragma unroll
    for (int c = 0; c < NC; ++c) {
        int s = (b * NC + c) * HH + h;
        g_carry[s] = carry;
        carry = fmaf(g_A[s], carry, g_Bc[s]);
    }
}

// ---------------- scan pass 3: apply carries, write output ----------------
__global__ __launch_bounds__(256)
void scan_apply(float* __restrict__ out) {
    int idx = blockIdx.x * blockDim.x + threadIdx.x;   // (b, c, h)
    int h = idx & (HH - 1);
    int c = (idx >> 10) & (NC - 1);
    int b = idx >> 15;
    size_t base = ((size_t)(b * TT + c * CL)) * HH + h;
    float hc = g_carry[(b * NC + c) * HH + h];
#pragma unroll 8
    for (int i = 0; i < CL; ++i) {
        float a = g_a[base + (size_t)i * HH];
        float bb = g_b[base + (size_t)i * HH];
        hc = fmaf(a, hc, bb);
        out[base + (size_t)i * HH] = hc;
    }
}

extern "C" void kernel_launch(void* const* d_in, const int* in_sizes, int n_in,
                              void* d_out, int out_size) {
    const float* x  = (const float*)d_in[0];
    const float* h0 = (const float*)d_in[1];
    const float* Wz = (const float*)d_in[2];
    const float* bz = (const float*)d_in[3];
    const float* Wh = (const float*)d_in[4];
    const float* bh = (const float*)d_in[5];
    float* out = (float*)d_out;

    __half *x16, *wz, *wh;
    cudaGetSymbolAddress((void**)&x16, g_x16);
    cudaGetSymbolAddress((void**)&wz,  g_wz);
    cudaGetSymbolAddress((void**)&wh,  g_wh);

    cvt_kernel<<<(int)(((size_t)MTOT * II) / 1024), 256>>>(x, x16);
    cvt_kernel<<<(HH * II) / 1024, 256>>>(Wz, wz);
    cvt_kernel<<<(HH * II) / 1024, 256>>>(Wh, wh);

    cudaFuncSetAttribute(gemm_mma_kernel, cudaFuncAttributeMaxDynamicSharedMemorySize, SMEM_TOTAL);
    dim3 ggrid(HH / 128, MTOT / 128);   // x = n-block (8), y = m-block (256)
    gemm_mma_kernel<<<ggrid, 256, SMEM_TOTAL>>>(bz, bh);

    scan_chunk_combine<<<(BB * HH) / 256, 256>>>(h0);
    scan_apply<<<(BB * NC * HH) / 256, 256>>>(out);
}